// round 13
// baseline (speedup 1.0000x reference)
#include <cuda_runtime.h>
#include <cuda_bf16.h>
#include <cuda_fp16.h>
#include <cstdint>

#define NN 50000
#define EE 800000
#define CC 128
#define GG 128
#define LD0 512
#define LD1 256
#define NC (NN*CC)

// ---------------- scratch (static device globals; no allocation) ----------------
__device__ int    g_deg[NN];
__device__ int    g_rowptr[NN + 1];
__device__ int    g_cursor[NN];
__device__ int    g_bsum[64];
__device__ int    g_boff[64];
__device__ float4 g_csr[EE];            // {src_as_float, ea0, ea1, ea2} in dst-CSR order
__device__ float  g_h[NN * CC];         // final-layer fp32 output (for pool)
__device__ float  g_q[NN * CC];         // Q plane fp32
__device__ float  g_s[NN * CC];         // S (skip) plane fp32
__device__ __align__(16) __half g_kv[NN * 256];  // interleaved K/V fp16: node-> 32 groups of [k0..3, v0..3]
__device__ __nv_bfloat16 g_ah[NN * CC]; // bf16 hi plane of activations
__device__ __nv_bfloat16 g_al[NN * CC]; // bf16 lo plane
__device__ __nv_bfloat16 g_bt[4 * CC * 384]; // W^T planes [mat][c][k0..383] = [Bh|Bh|Bl]
__device__ float  g_pool[GG * CC];
__device__ float  g_m0[GG * LD0];
__device__ float  g_m1[GG * LD1];

// ============================ mma.sync helpers =================================
__device__ __forceinline__ uint32_t smem_u32(const void* p) {
    uint32_t a;
    asm("{ .reg .u64 t; cvta.to.shared.u64 t, %1; cvt.u32.u64 %0, t; }" : "=r"(a) : "l"(p));
    return a;
}

__device__ __forceinline__ void ldsm_x4(uint32_t addr, uint32_t& r0, uint32_t& r1,
                                        uint32_t& r2, uint32_t& r3) {
    asm volatile("ldmatrix.sync.aligned.m8n8.x4.shared.b16 {%0,%1,%2,%3}, [%4];"
                 : "=r"(r0), "=r"(r1), "=r"(r2), "=r"(r3) : "r"(addr));
}

__device__ __forceinline__ void mma16816(float* c, const uint32_t* a, const uint32_t* b) {
    asm volatile(
        "mma.sync.aligned.m16n8k16.row.col.f32.bf16.bf16.f32 "
        "{%0,%1,%2,%3}, {%4,%5,%6,%7}, {%8,%9}, {%0,%1,%2,%3};"
        : "+f"(c[0]), "+f"(c[1]), "+f"(c[2]), "+f"(c[3])
        : "r"(a[0]), "r"(a[1]), "r"(a[2]), "r"(a[3]), "r"(b[0]), "r"(b[1]));
}

// ---------------- CSR build ----------------
__global__ void k_zero_deg() {
    int i = blockIdx.x * blockDim.x + threadIdx.x;
    if (i < NN) g_deg[i] = 0;
}

__global__ void k_count(const int* __restrict__ dst) {
    int i = blockIdx.x * blockDim.x + threadIdx.x;
    if (i < EE) atomicAdd(&g_deg[dst[i]], 1);
}

__global__ void k_scan1() {
    __shared__ int s[1024];
    int i = blockIdx.x * 1024 + threadIdx.x;
    int v = (i < NN) ? g_deg[i] : 0;
    s[threadIdx.x] = v;
    __syncthreads();
    #pragma unroll
    for (int off = 1; off < 1024; off <<= 1) {
        int t = (threadIdx.x >= off) ? s[threadIdx.x - off] : 0;
        __syncthreads();
        s[threadIdx.x] += t;
        __syncthreads();
    }
    if (i < NN) g_rowptr[i + 1] = s[threadIdx.x];
    if (threadIdx.x == 1023) g_bsum[blockIdx.x] = s[1023];
    if (i == 0) g_rowptr[0] = 0;
}

__global__ void k_scan2(int nb) {
    __shared__ int s[64];
    int t = threadIdx.x;
    s[t] = (t < nb) ? g_bsum[t] : 0;
    __syncthreads();
    if (t == 0) {
        int run = 0;
        for (int b = 0; b < nb; b++) { g_boff[b] = run; run += s[b]; }
    }
}

// scan3 + cursor init fused
__global__ void k_scan3() {
    int i = blockIdx.x * blockDim.x + threadIdx.x;
    if (i < NN) {
        int v = g_rowptr[i + 1] + g_boff[((unsigned)i) >> 10];
        g_rowptr[i + 1] = v;
        g_cursor[i + 1 < NN ? i + 1 : 0] = (i + 1 < NN) ? v : g_cursor[0];
        if (i + 1 < NN) g_cursor[i + 1] = v;
        if (i == 0) g_cursor[0] = 0;
    }
}

__global__ void k_fill(const int* __restrict__ src, const int* __restrict__ dst,
                       const float* __restrict__ ea) {
    int i = blockIdx.x * blockDim.x + threadIdx.x;
    if (i < EE) {
        int d = dst[i];
        int p = atomicAdd(&g_cursor[d], 1);
        g_csr[p] = make_float4(__int_as_float(src[i]), ea[3 * i], ea[3 * i + 1], ea[3 * i + 2]);
    }
}

// ---------------- layer-0 projection (din = 4) ----------------
__global__ __launch_bounds__(256) void k_proj0(
    const float* __restrict__ x,
    const float* __restrict__ Wq, const float* __restrict__ bq,
    const float* __restrict__ Wk, const float* __restrict__ bk,
    const float* __restrict__ Wv, const float* __restrict__ bv,
    const float* __restrict__ Ws, const float* __restrict__ bs)
{
    int idx = blockIdx.x * 256 + threadIdx.x;
    if (idx >= NN * 512) return;
    int n  = idx >> 9;
    int c  = idx & 511;
    int mat = c >> 7, cc = c & 127;
    const float* W = (mat == 0) ? Wq : (mat == 1) ? Wk : (mat == 2) ? Wv : Ws;
    const float* b = (mat == 0) ? bq : (mat == 1) ? bk : (mat == 2) ? bv : bs;
    float x0 = x[n * 4 + 0], x1 = x[n * 4 + 1], x2 = x[n * 4 + 2], x3 = x[n * 4 + 3];
    float v = b[cc];
    v = fmaf(x0, W[cc], v);
    v = fmaf(x1, W[128 + cc], v);
    v = fmaf(x2, W[256 + cc], v);
    v = fmaf(x3, W[384 + cc], v);
    if (mat == 0)      g_q[n * 128 + cc] = v;
    else if (mat == 3) g_s[n * 128 + cc] = v;
    else {
        int slot = (cc >> 2) * 8 + (cc & 3) + ((mat == 2) ? 4 : 0);
        g_kv[n * 256 + slot] = __float2half_rn(v);
    }
}

// ---------------- prep B: transpose weights into [mat][c][k 0..383] bf16 ----------------
__global__ __launch_bounds__(256) void k_prep_b(
    const float* __restrict__ W0, const float* __restrict__ W1,
    const float* __restrict__ W2, const float* __restrict__ W3)
{
    int i = blockIdx.x * 256 + threadIdx.x;     // 4*128*384 = 196608
    if (i >= 4 * 128 * 384) return;
    int mat = i / (128 * 384);
    int rem = i % (128 * 384);
    int c = rem / 384;
    int k = rem % 384;
    const float* W = (mat == 0) ? W0 : (mat == 1) ? W1 : (mat == 2) ? W2 : W3;
    int ksrc = (k < 128) ? k : (k < 256) ? (k - 128) : (k - 256);
    float v = W[ksrc * 128 + c];
    __nv_bfloat16 out;
    if (k < 256) out = __float2bfloat16(v);
    else {
        __nv_bfloat16 h = __float2bfloat16(v);
        out = __float2bfloat16(v - __bfloat162float(h));
    }
    g_bt[mat * (128 * 384) + c * 384 + k] = out;
}

// ---------------- mma.sync split-bf16 GEMM: out[128,128] tile, K=384 ----------------
#define ASTR 72
__global__ __launch_bounds__(256) void k_gemm_mma(
    const float* __restrict__ b0, const float* __restrict__ b1,
    const float* __restrict__ b2, const float* __restrict__ b3)
{
    __shared__ __nv_bfloat16 sA[128 * ASTR];
    __shared__ __nv_bfloat16 sB[128 * ASTR];
    __shared__ float sbias[128];

    const int tid = threadIdx.x, wid = tid >> 5, lane = tid & 31;
    const int mat = blockIdx.y;
    const int m0 = blockIdx.x * 128;
    const __nv_bfloat16* Bt = g_bt + mat * (128 * 384);
    const float* bias = (mat == 0) ? b0 : (mat == 1) ? b1 : (mat == 2) ? b2 : b3;

    const int warpM = (wid >> 2) * 64;
    const int warpN = (wid & 3) * 32;

    if (tid < 128) sbias[tid] = bias[tid];

    float acc[4][4][4];
    #pragma unroll
    for (int i = 0; i < 4; i++)
        #pragma unroll
        for (int j = 0; j < 4; j++)
            #pragma unroll
            for (int k = 0; k < 4; k++) acc[i][j][k] = 0.f;

    const int q = lane >> 3, r = lane & 7;
    const uint32_t sA_base = smem_u32(sA);
    const uint32_t sB_base = smem_u32(sB);
    const uint32_t a_lane = sA_base + (uint32_t)(((warpM + (q & 1) * 8 + r) * ASTR + (q >> 1) * 8) * 2);
    const uint32_t b_lane = sB_base + (uint32_t)(((warpN + (q >> 1) * 8 + r) * ASTR + (q & 1) * 8) * 2);

    for (int kc = 0; kc < 6; kc++) {
        const __nv_bfloat16* Ap = (kc == 2 || kc == 3) ? g_al : g_ah;
        const int half = kc & 1;
        __syncthreads();
        #pragma unroll
        for (int i = 0; i < 4; i++) {
            int idx = tid + i * 256;
            int row = idx >> 3, j = idx & 7;
            int node = m0 + row;
            uint4 v = make_uint4(0, 0, 0, 0);
            if (node < NN) v = reinterpret_cast<const uint4*>(Ap)[node * 16 + half * 8 + j];
            *reinterpret_cast<uint4*>(&sA[row * ASTR + j * 8]) = v;
        }
        #pragma unroll
        for (int i = 0; i < 4; i++) {
            int idx = tid + i * 256;
            int row = idx >> 3, j = idx & 7;
            uint4 v = reinterpret_cast<const uint4*>(Bt)[row * 48 + kc * 8 + j];
            *reinterpret_cast<uint4*>(&sB[row * ASTR + j * 8]) = v;
        }
        __syncthreads();

        #pragma unroll
        for (int ks = 0; ks < 4; ks++) {
            uint32_t af[4][4], bf[4][2];
            #pragma unroll
            for (int mi = 0; mi < 4; mi++)
                ldsm_x4(a_lane + (uint32_t)((mi * 16 * ASTR + ks * 16) * 2),
                        af[mi][0], af[mi][1], af[mi][2], af[mi][3]);
            #pragma unroll
            for (int pr = 0; pr < 2; pr++)
                ldsm_x4(b_lane + (uint32_t)((pr * 16 * ASTR + ks * 16) * 2),
                        bf[pr * 2][0], bf[pr * 2][1], bf[pr * 2 + 1][0], bf[pr * 2 + 1][1]);
            #pragma unroll
            for (int mi = 0; mi < 4; mi++)
                #pragma unroll
                for (int nj = 0; nj < 4; nj++)
                    mma16816(acc[mi][nj], af[mi], bf[nj]);
        }
    }

    // epilogue: Q/S -> fp32 planes, K/V -> interleaved fp16 g_kv
    const int trow = lane >> 2, tcol = 2 * (lane & 3);
    const bool is_half = (mat == 1 || mat == 2);
    float* Outf = (mat == 0) ? g_q : g_s;
    const int vofs = (mat == 2) ? 4 : 0;
    #pragma unroll
    for (int mi = 0; mi < 4; mi++) {
        int row_a = m0 + warpM + mi * 16 + trow;
        int row_b = row_a + 8;
        #pragma unroll
        for (int nj = 0; nj < 4; nj++) {
            int col = warpN + nj * 8 + tcol;
            float bx = sbias[col], by = sbias[col + 1];
            int slot = (col >> 2) * 8 + (col & 3) + vofs;
            if (row_a < NN) {
                float ox = acc[mi][nj][0] + bx, oy = acc[mi][nj][1] + by;
                if (is_half) *reinterpret_cast<__half2*>(&g_kv[row_a * 256 + slot]) = __floats2half2_rn(ox, oy);
                else *reinterpret_cast<float2*>(&Outf[row_a * 128 + col]) = make_float2(ox, oy);
            }
            if (row_b < NN) {
                float ox = acc[mi][nj][2] + bx, oy = acc[mi][nj][3] + by;
                if (is_half) *reinterpret_cast<__half2*>(&g_kv[row_b * 256 + slot]) = __floats2half2_rn(ox, oy);
                else *reinterpret_cast<float2*>(&Outf[row_b * 128 + col]) = make_float2(ox, oy);
            }
        }
    }
}

// ---------------- warp-per-node aggregation -------------------------------------
// Edge-emb algebra: e = ea@We  =>  q.e = ea.(q@We) ;  sum w(v+e) = sum w v + (sum w ea)@We
// Per edge: 1 broadcast LDG (csr) + 1 LDG.128 (interleaved K/V). No per-edge e compute.
// mode 0: write bf16 hi/lo planes (feeds next GEMM). mode 1: write fp32 g_h (pool).
__global__ __launch_bounds__(256) void k_agg(const float* __restrict__ We, int mode)
{
    __shared__ float sWe[384];
    for (int i = threadIdx.x; i < 384; i += 256) sWe[i] = We[i];
    __syncthreads();

    int warp = threadIdx.x >> 5, lane = threadIdx.x & 31;
    int node = blockIdx.x * 8 + warp;
    if (node >= NN) return;

    int o = node * 128;
    int c4 = lane * 4;
    float4 q  = *reinterpret_cast<const float4*>(g_q + o + c4);
    float4 w0 = *reinterpret_cast<const float4*>(sWe + c4);
    float4 w1 = *reinterpret_cast<const float4*>(sWe + 128 + c4);
    float4 w2 = *reinterpret_cast<const float4*>(sWe + 256 + c4);

    // precompute qW_j = q . We[:,j-th attr col] (3 warp reductions)
    float qw0 = fmaf(q.x, w0.x, fmaf(q.y, w0.y, fmaf(q.z, w0.z, q.w * w0.w)));
    float qw1 = fmaf(q.x, w1.x, fmaf(q.y, w1.y, fmaf(q.z, w1.z, q.w * w1.w)));
    float qw2 = fmaf(q.x, w2.x, fmaf(q.y, w2.y, fmaf(q.z, w2.z, q.w * w2.w)));
    #pragma unroll
    for (int off = 16; off >= 1; off >>= 1) {
        qw0 += __shfl_xor_sync(0xffffffffu, qw0, off);
        qw1 += __shfl_xor_sync(0xffffffffu, qw1, off);
        qw2 += __shfl_xor_sync(0xffffffffu, qw2, off);
    }

    float d = 0.f, s0 = 0.f, s1 = 0.f, s2 = 0.f;
    float4 a = make_float4(0.f, 0.f, 0.f, 0.f);

    int beg = g_rowptr[node], end = g_rowptr[node + 1];

    #pragma unroll 4
    for (int e = beg; e < end; e++) {
        float4 ed = g_csr[e];
        int src = __float_as_int(ed.x);
        uint4 kvv = *reinterpret_cast<const uint4*>(g_kv + src * 256 + lane * 8);
        float2 k01 = __half22float2(*reinterpret_cast<__half2*>(&kvv.x));
        float2 k23 = __half22float2(*reinterpret_cast<__half2*>(&kvv.y));
        float2 v01 = __half22float2(*reinterpret_cast<__half2*>(&kvv.z));
        float2 v23 = __half22float2(*reinterpret_cast<__half2*>(&kvv.w));

        float p = fmaf(q.x, k01.x, fmaf(q.y, k01.y, fmaf(q.z, k23.x, q.w * k23.y)));
        p += __shfl_xor_sync(0xffffffffu, p, 16);
        p += __shfl_xor_sync(0xffffffffu, p, 8);
        p += __shfl_xor_sync(0xffffffffu, p, 4);
        p += __shfl_xor_sync(0xffffffffu, p, 2);
        p += __shfl_xor_sync(0xffffffffu, p, 1);

        float logit = (p + fmaf(ed.y, qw0, fmaf(ed.z, qw1, ed.w * qw2))) * 0.08838834764831845f;
        float w = __expf(logit);
        d += w;
        s0 = fmaf(w, ed.y, s0);
        s1 = fmaf(w, ed.z, s1);
        s2 = fmaf(w, ed.w, s2);
        a.x = fmaf(w, v01.x, a.x);
        a.y = fmaf(w, v01.y, a.y);
        a.z = fmaf(w, v23.x, a.z);
        a.w = fmaf(w, v23.y, a.w);
    }

    float inv = (end > beg) ? (1.0f / fmaxf(d, 1e-35f)) : 0.f;
    float4 s = *reinterpret_cast<const float4*>(g_s + o + c4);
    float4 r;
    float nx = fmaf(s0, w0.x, fmaf(s1, w1.x, fmaf(s2, w2.x, a.x)));
    float ny = fmaf(s0, w0.y, fmaf(s1, w1.y, fmaf(s2, w2.y, a.y)));
    float nz = fmaf(s0, w0.z, fmaf(s1, w1.z, fmaf(s2, w2.z, a.z)));
    float nw = fmaf(s0, w0.w, fmaf(s1, w1.w, fmaf(s2, w2.w, a.w)));
    r.x = fmaf(nx, inv, s.x); r.x = (r.x > 0.f) ? r.x : 0.01f * r.x;
    r.y = fmaf(ny, inv, s.y); r.y = (r.y > 0.f) ? r.y : 0.01f * r.y;
    r.z = fmaf(nz, inv, s.z); r.z = (r.z > 0.f) ? r.z : 0.01f * r.z;
    r.w = fmaf(nw, inv, s.w); r.w = (r.w > 0.f) ? r.w : 0.01f * r.w;

    if (mode == 0) {
        __nv_bfloat16 h0 = __float2bfloat16(r.x), h1 = __float2bfloat16(r.y);
        __nv_bfloat16 h2 = __float2bfloat16(r.z), h3 = __float2bfloat16(r.w);
        __nv_bfloat16 l0 = __float2bfloat16(r.x - __bfloat162float(h0));
        __nv_bfloat16 l1 = __float2bfloat16(r.y - __bfloat162float(h1));
        __nv_bfloat16 l2 = __float2bfloat16(r.z - __bfloat162float(h2));
        __nv_bfloat16 l3 = __float2bfloat16(r.w - __bfloat162float(h3));
        __nv_bfloat162 hh0(h0, h1), hh1(h2, h3), ll0(l0, l1), ll1(l2, l3);
        uint2 hv, lv;
        hv.x = *reinterpret_cast<uint32_t*>(&hh0); hv.y = *reinterpret_cast<uint32_t*>(&hh1);
        lv.x = *reinterpret_cast<uint32_t*>(&ll0); lv.y = *reinterpret_cast<uint32_t*>(&ll1);
        *reinterpret_cast<uint2*>(g_ah + o + c4) = hv;
        *reinterpret_cast<uint2*>(g_al + o + c4) = lv;
    } else {
        *reinterpret_cast<float4*>(g_h + o + c4) = r;
    }
}

// ---------------- pool (sorted batch -> segmented reduce, no atomics) ----------------
__global__ __launch_bounds__(128) void k_pool2(const int* __restrict__ batch) {
    int g = blockIdx.x, t = threadIdx.x;
    int lo = 0, hi = NN;
    while (lo < hi) { int mid = (lo + hi) >> 1; if (batch[mid] < g) lo = mid + 1; else hi = mid; }
    int beg = lo;
    hi = NN;
    while (lo < hi) { int mid = (lo + hi) >> 1; if (batch[mid] < g + 1) lo = mid + 1; else hi = mid; }
    int end = lo;
    float acc = 0.f;
    for (int r = beg; r < end; r++) acc += g_h[r * 128 + t];
    g_pool[g * 128 + t] = acc;
}

// ---------------- MLP head ----------------
__global__ __launch_bounds__(512) void k_mlp0(const float* __restrict__ W, const float* __restrict__ b) {
    __shared__ float s[128];
    int row = blockIdx.x, t = threadIdx.x;
    if (t < 128) s[t] = g_pool[row * 128 + t];
    __syncthreads();
    float acc = b[t];
    #pragma unroll 8
    for (int k = 0; k < 128; k++) acc = fmaf(s[k], W[k * 512 + t], acc);
    g_m0[row * 512 + t] = fmaxf(acc, 0.f);
}

__global__ __launch_bounds__(256) void k_mlp1(const float* __restrict__ W, const float* __restrict__ b) {
    __shared__ float s[512];
    int row = blockIdx.x, t = threadIdx.x;
    s[t] = g_m0[row * 512 + t];
    s[t + 256] = g_m0[row * 512 + t + 256];
    __syncthreads();
    float acc = b[t];
    #pragma unroll 8
    for (int k = 0; k < 512; k++) acc = fmaf(s[k], W[k * 256 + t], acc);
    g_m1[row * 256 + t] = fmaxf(acc, 0.f);
}

__global__ __launch_bounds__(256) void k_mlp2(const float* __restrict__ W, const float* __restrict__ b,
                                              float* __restrict__ out) {
    int t = threadIdx.x;
    int row = t >> 1, p = t & 1;
    float acc = b[p];
    for (int k = 0; k < 256; k++) acc = fmaf(g_m1[row * 256 + k], W[k * 2 + p], acc);
    out[row * 2 + p] = acc;
}

// ---------------- launch ----------------
extern "C" void kernel_launch(void* const* d_in, const int* in_sizes, int n_in,
                              void* d_out, int out_size) {
    const float* x     = (const float*)d_in[0];
    const int*   ei    = (const int*)  d_in[1];
    const float* ea    = (const float*)d_in[2];
    const int*   batch = (const int*)  d_in[3];

    const float* Wq0 = (const float*)d_in[4];  const float* bq0 = (const float*)d_in[5];
    const float* Wk0 = (const float*)d_in[6];  const float* bk0 = (const float*)d_in[7];
    const float* Wv0 = (const float*)d_in[8];  const float* bv0 = (const float*)d_in[9];
    const float* We0 = (const float*)d_in[10];
    const float* Ws0 = (const float*)d_in[11]; const float* bs0 = (const float*)d_in[12];

    const float* Wq1 = (const float*)d_in[13]; const float* bq1 = (const float*)d_in[14];
    const float* Wk1 = (const float*)d_in[15]; const float* bk1 = (const float*)d_in[16];
    const float* Wv1 = (const float*)d_in[17]; const float* bv1 = (const float*)d_in[18];
    const float* We1 = (const float*)d_in[19];
    const float* Ws1 = (const float*)d_in[20]; const float* bs1 = (const float*)d_in[21];

    const float* Wl0 = (const float*)d_in[22]; const float* bl0 = (const float*)d_in[23];
    const float* Wl1 = (const float*)d_in[24]; const float* bl1 = (const float*)d_in[25];
    const float* Wl2 = (const float*)d_in[26]; const float* bl2 = (const float*)d_in[27];

    const int* srcp = ei;
    const int* dstp = ei + EE;

    // ---- CSR build (once; graph shared by all 3 layers) ----
    k_zero_deg<<<(NN + 255) / 256, 256>>>();
    k_count<<<(EE + 255) / 256, 256>>>(dstp);
    k_scan1<<<(NN + 1023) / 1024, 1024>>>();
    k_scan2<<<1, 64>>>((NN + 1023) / 1024);
    k_scan3<<<(NN + 255) / 256, 256>>>();
    k_fill<<<(EE + 255) / 256, 256>>>(srcp, dstp, ea);

    // ---- prep transposed bf16 weight planes (layers 1&2 share weights) ----
    k_prep_b<<<(4 * 128 * 384 + 255) / 256, 256>>>(Wq1, Wk1, Wv1, Ws1);

    dim3 gemm_grid((NN + 127) / 128, 4);
    int  agg_grid = (NN + 7) / 8;

    // ---- layer 0 ----
    k_proj0<<<(NN * 512 + 255) / 256, 256>>>(x, Wq0, bq0, Wk0, bk0, Wv0, bv0, Ws0, bs0);
    k_agg<<<agg_grid, 256>>>(We0, /*mode=*/0);          // -> g_ah/g_al

    // ---- layer 1 ----
    k_gemm_mma<<<gemm_grid, 256>>>(bq1, bk1, bv1, bs1); // planes -> Q/KV/S
    k_agg<<<agg_grid, 256>>>(We1, /*mode=*/0);          // -> g_ah/g_al

    // ---- layer 2 (same weights) ----
    k_gemm_mma<<<gemm_grid, 256>>>(bq1, bk1, bv1, bs1); // planes -> Q/KV/S
    k_agg<<<agg_grid, 256>>>(We1, /*mode=*/1);          // -> g_h (fp32)

    // ---- pool + MLP ----
    k_pool2<<<GG, 128>>>(batch);
    k_mlp0<<<GG, 512>>>(Wl0, bl0);
    k_mlp1<<<GG, 256>>>(Wl1, bl1);
    k_mlp2<<<1, 256>>>(Wl2, bl2, (float*)d_out);
}